// round 1
// baseline (speedup 1.0000x reference)
#include <cuda_runtime.h>
#include <cuda_bf16.h>

#define CH   64
#define TT   2048
#define BM   64
#define BN   64
#define NTH  256
#define NB   64   // batch*heads

// Flash-attention fp32 baseline.
// Grid: (TT/BM, NB). Block: 256 threads = 16x16 thread tiles, each thread owns
// a 4x4 register tile (rows t = ty*4.., cols s or c = tx*4..).
// SMEM: sQ[64][64] (c-major, t contiguous), sK likewise, sV with XOR swizzle,
// sP[64][64] (t-major, s contiguous).
__global__ __launch_bounds__(NTH) void attn_kernel(const float* __restrict__ qkv,
                                                   float* __restrict__ out) {
    extern __shared__ float smem[];
    float* sQ = smem;             // 4096 floats
    float* sK = smem + 4096;
    float* sV = smem + 8192;      // swizzled: v[c][s] at column s ^ (c & 28)
    float* sP = smem + 12288;

    const int b     = blockIdx.y;
    const int qbase = blockIdx.x * BM;
    const float* qp = qkv + (size_t)b * 3 * CH * TT;
    const float* kp = qp + (size_t)CH * TT;
    const float* vp = qp + (size_t)2 * CH * TT;

    const int tid = threadIdx.x;
    const int tx  = tid & 15;
    const int ty  = tid >> 4;
    const int t0  = ty * 4;   // local query rows
    const int c0  = tx * 4;   // key cols (phase 1) / out channels (phase 2)

    // ---- load Q tile: sQ[c][t] ----
    #pragma unroll
    for (int r = ty; r < CH; r += 16) {
        *(float4*)(sQ + r * 64 + tx * 4) =
            *(const float4*)(qp + (size_t)r * TT + qbase + tx * 4);
    }

    float acc[4][4];
    #pragma unroll
    for (int i = 0; i < 4; i++)
        #pragma unroll
        for (int j = 0; j < 4; j++) acc[i][j] = 0.f;
    float mrow[4], lrow[4];
    #pragma unroll
    for (int i = 0; i < 4; i++) { mrow[i] = -1e30f; lrow[i] = 0.f; }

    for (int kt = 0; kt < TT / BN; ++kt) {
        const int kb = kt * BN;

        __syncthreads();  // previous iteration done reading sK/sV/sP
        #pragma unroll
        for (int r = ty; r < CH; r += 16) {
            *(float4*)(sK + r * 64 + tx * 4) =
                *(const float4*)(kp + (size_t)r * TT + kb + tx * 4);
            const int scol = (tx * 4) ^ (r & 28);
            *(float4*)(sV + r * 64 + scol) =
                *(const float4*)(vp + (size_t)r * TT + kb + tx * 4);
        }
        __syncthreads();

        // ---- scores: sc[i][j] = sum_c q[c][t0+i] * k[c][c0+j] ----
        float sc[4][4];
        #pragma unroll
        for (int i = 0; i < 4; i++)
            #pragma unroll
            for (int j = 0; j < 4; j++) sc[i][j] = 0.f;

        #pragma unroll 8
        for (int c = 0; c < CH; ++c) {
            float4 qv = *(const float4*)(sQ + c * 64 + t0);
            float4 kv = *(const float4*)(sK + c * 64 + c0);
            const float qa[4] = {qv.x, qv.y, qv.z, qv.w};
            const float ka[4] = {kv.x, kv.y, kv.z, kv.w};
            #pragma unroll
            for (int i = 0; i < 4; i++)
                #pragma unroll
                for (int j = 0; j < 4; j++)
                    sc[i][j] = fmaf(qa[i], ka[j], sc[i][j]);
        }

        // ---- online softmax (rows of a tile live in one 16-lane group) ----
        #pragma unroll
        for (int i = 0; i < 4; i++) {
            float mx = -1e30f;
            #pragma unroll
            for (int j = 0; j < 4; j++) {
                sc[i][j] *= 0.125f;           // (ch^-1/4)^2 = 1/sqrt(64)
                mx = fmaxf(mx, sc[i][j]);
            }
            #pragma unroll
            for (int off = 8; off >= 1; off >>= 1)
                mx = fmaxf(mx, __shfl_xor_sync(0xffffffffu, mx, off));
            const float mnew = fmaxf(mrow[i], mx);
            const float corr = __expf(mrow[i] - mnew);
            float psum = 0.f;
            #pragma unroll
            for (int j = 0; j < 4; j++) {
                const float p = __expf(sc[i][j] - mnew);
                psum += p;
                sP[(t0 + i) * 64 + c0 + j] = p;
            }
            #pragma unroll
            for (int off = 8; off >= 1; off >>= 1)
                psum += __shfl_xor_sync(0xffffffffu, psum, off);
            lrow[i] = lrow[i] * corr + psum;
            mrow[i] = mnew;
            #pragma unroll
            for (int j = 0; j < 4; j++) acc[i][j] *= corr;
        }
        __syncthreads();  // sP fully written

        // ---- acc[i][j] += sum_s P[t0+i][s] * V[c0+j][s] ----
        #pragma unroll 4
        for (int s4 = 0; s4 < BN; s4 += 4) {
            float pv[4][4], vv[4][4];
            #pragma unroll
            for (int i = 0; i < 4; i++)
                *(float4*)pv[i] = *(const float4*)(sP + (t0 + i) * 64 + s4);
            #pragma unroll
            for (int j = 0; j < 4; j++) {
                const int c    = c0 + j;
                const int scol = s4 ^ (c & 28);
                *(float4*)vv[j] = *(const float4*)(sV + c * 64 + scol);
            }
            #pragma unroll
            for (int i = 0; i < 4; i++)
                #pragma unroll
                for (int j = 0; j < 4; j++)
                    #pragma unroll
                    for (int u = 0; u < 4; u++)
                        acc[i][j] = fmaf(pv[i][u], vv[j][u], acc[i][j]);
        }
    }

    // ---- epilogue: out[b][c][t] = acc / l ----
    float inv[4];
    #pragma unroll
    for (int i = 0; i < 4; i++) inv[i] = 1.0f / lrow[i];
    float* op = out + (size_t)b * CH * TT;
    #pragma unroll
    for (int j = 0; j < 4; j++) {
        float4 o;
        o.x = acc[0][j] * inv[0];
        o.y = acc[1][j] * inv[1];
        o.z = acc[2][j] * inv[2];
        o.w = acc[3][j] * inv[3];
        *(float4*)(op + (size_t)(c0 + j) * TT + qbase + t0) = o;
    }
}

extern "C" void kernel_launch(void* const* d_in, const int* in_sizes, int n_in,
                              void* d_out, int out_size) {
    const float* qkv = (const float*)d_in[0];
    float* out = (float*)d_out;
    cudaFuncSetAttribute(attn_kernel, cudaFuncAttributeMaxDynamicSharedMemorySize,
                         64 * 1024);
    dim3 grid(TT / BM, NB);
    attn_kernel<<<grid, NTH, 64 * 1024>>>(qkv, out);
}